// round 2
// baseline (speedup 1.0000x reference)
#include <cuda_runtime.h>
#include <cuda_fp16.h>
#include <cstdint>

// ---------------------------------------------------------------------------
// Problem: out (32,4096,512) f32, hidden (2,32,512), W (512,512), b(512), v(512)
// Output = [context (32*512) | attn (32*4096)] f32.
//
// energy = tanh(out @ W^T + b + hidden[-1]); scores = energy @ v;
// attn = softmax_s(scores); context = attn @ out.
//
// Strategy: 1024 CTAs, one 128-row tile each. fp16 HMMA (mma.sync m16n8k16,
// base-target — tcgen05 is ptxas-gated behind sm_103a which this toolchain
// does not emit). A tile resident fp16 in SMEM; W streamed in 32-col chunks,
// cp.async double-buffered. tanh+dot-v folded per chunk. Tile-local softmax
// with global merge (flash-style m/l/partial-context).
// ---------------------------------------------------------------------------
#define B_DIM   32
#define S_DIM   4096
#define H_DIM   512
#define ROWS    128
#define NTILES  1024
#define NC      16                  // 16 N-chunks of 32 cols

// SMEM layout (bytes)
#define SM_RED   0                  // 16 floats reduction scratch
#define SM_SC    64                 // 128 f32 row scores
#define SM_SW    576                // 128 f32 softmax weights
#define SM_BIAS  1088               // 512 f32
#define SM_V     3136               // 512 f32
#define SM_A     8192               // 128 rows x 512 cols fp16 (1024B/row, swizzled)
#define SM_WB    139264             // W chunk double buffer: 2 x 32768
#define SM_TOTAL 204800

#define SWZ(byte_in_row, row) ((byte_in_row) ^ (((row) & 7) << 4))

// -------------------- device-global scratch --------------------------------
__device__ __align__(16) unsigned char g_W16[H_DIM * H_DIM * 2]; // fp16, swizzled rows
__device__ float g_bias[B_DIM * H_DIM];
__device__ float g_scores[B_DIM * S_DIM];
__device__ float g_pm[NTILES];
__device__ float g_pl[NTILES];
__device__ float g_pc[NTILES * H_DIM];

// -------------------- helpers ----------------------------------------------
__device__ __forceinline__ uint32_t smem_u32(const void* p) {
    uint32_t a;
    asm("{ .reg .u64 t; cvta.to.shared.u64 t, %1; cvt.u32.u64 %0, t; }"
        : "=r"(a) : "l"(p));
    return a;
}
__device__ __forceinline__ void cp_async16(uint32_t dst, const void* src) {
    asm volatile("cp.async.cg.shared.global [%0], [%1], 16;"
                 :: "r"(dst), "l"(__cvta_generic_to_global(src)) : "memory");
}
#define CP_COMMIT() asm volatile("cp.async.commit_group;" ::: "memory")
#define CP_WAIT0()  asm volatile("cp.async.wait_group 0;" ::: "memory")

#define LDSM_X4(r0, r1, r2, r3, addr)                                          \
    asm volatile("ldmatrix.sync.aligned.m8n8.x4.shared.b16 {%0,%1,%2,%3}, [%4];" \
                 : "=r"(r0), "=r"(r1), "=r"(r2), "=r"(r3) : "r"(addr))

#define MMA16816(c0, c1, c2, c3, a0, a1, a2, a3, b0, b1)                       \
    asm volatile("mma.sync.aligned.m16n8k16.row.col.f32.f16.f16.f32 "          \
                 "{%0,%1,%2,%3}, {%4,%5,%6,%7}, {%8,%9}, {%0,%1,%2,%3};"       \
                 : "+f"(c0), "+f"(c1), "+f"(c2), "+f"(c3)                      \
                 : "r"(a0), "r"(a1), "r"(a2), "r"(a3), "r"(b0), "r"(b1))

// tanh via MUFU exp + rcp: accurate to ~1e-7 rel, ~6 SASS ops.
__device__ __forceinline__ float tanh_fast(float x) {
    float e = __expf(2.0f * x);
    return 1.0f - __fdividef(2.0f, e + 1.0f);
}

// ---------------------------------------------------------------------------
// Kernel 0: prep — W f32 -> fp16 swizzled rows; bias = b + hidden[last].
// g_W16 layout: row n (o-dim), 1024 B/row; byte = n*1024 + SWZ(k*2, n).
// ---------------------------------------------------------------------------
__global__ void prep_kernel(const float* __restrict__ W,
                            const float* __restrict__ bvec,
                            const float* __restrict__ hidden,
                            int hid_off) {
    int idx = blockIdx.x * blockDim.x + threadIdx.x;
    int stride = gridDim.x * blockDim.x;
    for (int i = idx; i < H_DIM * H_DIM; i += stride) {
        int n = i >> 9, k = i & 511;
        uint32_t off = (uint32_t)n * 1024u + SWZ((uint32_t)(k * 2), n);
        *(__half*)(g_W16 + off) = __float2half_rn(W[i]);
    }
    for (int i = idx; i < B_DIM * H_DIM; i += stride)
        g_bias[i] = bvec[i & 511] + hidden[hid_off + i];
}

// ---------------------------------------------------------------------------
// Kernel 1: main
// ---------------------------------------------------------------------------
__global__ void __launch_bounds__(256, 1)
attn_main_kernel(const float* __restrict__ gout, const float* __restrict__ gv) {
    extern __shared__ char smem[];
    const uint32_t sb = smem_u32(smem);
    const int tid = threadIdx.x;
    const int wid = tid >> 5;
    const int lane = tid & 31;
    const int tile = blockIdx.x;
    const int bi = tile >> 5;
    const int ti = tile & 31;

    // ---- prefetch W chunk 0 (32 rows x 1024B = 32KB) ----
    {
        uint32_t dst = sb + SM_WB + tid * 16;
        const unsigned char* src = g_W16 + tid * 16;
#pragma unroll
        for (int j = 0; j < 8; j++)
            cp_async16(dst + j * 4096, src + j * 4096);
        CP_COMMIT();
    }

    // ---- bias + v into SMEM ----
    for (int i = tid; i < H_DIM; i += 256) {
        *(float*)(smem + SM_V + i * 4)    = gv[i];
        *(float*)(smem + SM_BIAS + i * 4) = g_bias[bi * H_DIM + i];
    }

    // ---- load A tile (128 x 512 f32) -> fp16 swizzled SMEM ----
    const float4* src4 =
        (const float4*)(gout + (size_t)(bi * S_DIM + ti * ROWS) * H_DIM);
#pragma unroll 4
    for (int j = tid; j < ROWS * 128; j += 256) {   // one float4 = 4 halves = 8B
        float4 f = src4[j];
        int r = j >> 7, c4 = j & 127;
        __half2 h01 = __floats2half2_rn(f.x, f.y);
        __half2 h23 = __floats2half2_rn(f.z, f.w);
        uint2 val;
        val.x = *reinterpret_cast<uint32_t*>(&h01);
        val.y = *reinterpret_cast<uint32_t*>(&h23);
        uint32_t off = (uint32_t)r * 1024u + SWZ((uint32_t)(c4 * 8), r);
        *(uint2*)(smem + SM_A + off) = val;
    }

    CP_WAIT0();
    __syncthreads();

    // ---- lane addressing for ldmatrix ----
    const int wr0 = wid * 16;
    const int a_row = wr0 + (lane & 7) + ((lane >> 3) & 1) * 8;
    const uint32_t a_base = sb + SM_A + a_row * 1024;
    const uint32_t a_sw   = (a_row & 7) << 4;
    const uint32_t a_t16  = (lane >> 4) * 16;        // k+8 half selector

    const int b_ln  = (lane & 7) + ((lane >> 4) & 1) * 8;
    const uint32_t b_sw  = (b_ln & 7) << 4;
    const uint32_t b_t16 = ((lane >> 3) & 1) * 16;

    float score_lo = 0.f, score_hi = 0.f;
    const float* sbias = (const float*)(smem + SM_BIAS);
    const float* sv    = (const float*)(smem + SM_V);

    for (int nc = 0; nc < NC; nc++) {
        const uint32_t wb = sb + SM_WB + (nc & 1) * 32768;

        // prefetch next W chunk into other buffer
        if (nc + 1 < NC) {
            uint32_t dst = sb + SM_WB + ((nc + 1) & 1) * 32768 + tid * 16;
            const unsigned char* s = g_W16 + (size_t)(nc + 1) * 32768 + tid * 16;
#pragma unroll
            for (int j = 0; j < 8; j++)
                cp_async16(dst + j * 4096, s + j * 4096);
            CP_COMMIT();
        }

        const uint32_t b_base0 = wb + b_ln * 1024;
        const uint32_t b_base1 = wb + (b_ln + 16) * 1024;

        float c0[4] = {0,0,0,0}, c1[4] = {0,0,0,0};
        float c2[4] = {0,0,0,0}, c3[4] = {0,0,0,0};

#pragma unroll 4
        for (uint32_t k2 = 0; k2 < 1024; k2 += 32) {   // k*2 bytes, 32 K-steps
            uint32_t a0, a1, a2, a3, b0, b1, b2, b3, b4, b5, b6, b7;
            LDSM_X4(a0, a1, a2, a3, a_base + (((k2 | a_t16)) ^ a_sw));
            LDSM_X4(b0, b1, b2, b3, b_base0 + (((k2 | b_t16)) ^ b_sw));
            LDSM_X4(b4, b5, b6, b7, b_base1 + (((k2 | b_t16)) ^ b_sw));
            MMA16816(c0[0], c0[1], c0[2], c0[3], a0, a1, a2, a3, b0, b1);
            MMA16816(c1[0], c1[1], c1[2], c1[3], a0, a1, a2, a3, b2, b3);
            MMA16816(c2[0], c2[1], c2[2], c2[3], a0, a1, a2, a3, b4, b5);
            MMA16816(c3[0], c3[1], c3[2], c3[3], a0, a1, a2, a3, b6, b7);
        }

        // epilogue: tanh + dot v (cols nc*32 + {0,8,16,24} + (lane%4)*2)
        {
            const int cb = nc * 32 + (lane & 3) * 2;
            float2 bb, vv;
#define EPI(CF, NO)                                                            \
            bb = *(const float2*)(sbias + cb + (NO));                          \
            vv = *(const float2*)(sv + cb + (NO));                             \
            score_lo += tanh_fast(CF[0] + bb.x) * vv.x                         \
                      + tanh_fast(CF[1] + bb.y) * vv.y;                        \
            score_hi += tanh_fast(CF[2] + bb.x) * vv.x                         \
                      + tanh_fast(CF[3] + bb.y) * vv.y;
            EPI(c0, 0) EPI(c1, 8) EPI(c2, 16) EPI(c3, 24)
#undef EPI
        }

        if (nc + 1 < NC) {
            CP_WAIT0();
            __syncthreads();
        }
    }

    // ---- reduce scores across quad lanes (cols) ----
    score_lo += __shfl_xor_sync(0xffffffffu, score_lo, 1);
    score_lo += __shfl_xor_sync(0xffffffffu, score_lo, 2);
    score_hi += __shfl_xor_sync(0xffffffffu, score_hi, 1);
    score_hi += __shfl_xor_sync(0xffffffffu, score_hi, 2);
    float* s_sc = (float*)(smem + SM_SC);
    if ((lane & 3) == 0) {
        int r = wr0 + (lane >> 2);
        s_sc[r]     = score_lo;
        s_sc[r + 8] = score_hi;
        g_scores[bi * S_DIM + ti * ROWS + r]     = score_lo;
        g_scores[bi * S_DIM + ti * ROWS + r + 8] = score_hi;
    }
    __syncthreads();

    // ---- tile-local softmax over 128 rows ----
    float* sred = (float*)(smem + SM_RED);
    float sc = (tid < 128) ? s_sc[tid] : -1e30f;
    float m = sc;
#pragma unroll
    for (int o = 16; o; o >>= 1) m = fmaxf(m, __shfl_xor_sync(0xffffffffu, m, o));
    if (lane == 0) sred[wid] = m;
    __syncthreads();
    float mt = fmaxf(fmaxf(sred[0], sred[1]), fmaxf(sred[2], sred[3]));

    float w = (tid < 128) ? __expf(sc - mt) : 0.f;
    float ls = w;
#pragma unroll
    for (int o = 16; o; o >>= 1) ls += __shfl_xor_sync(0xffffffffu, ls, o);
    if (lane == 0) sred[8 + wid] = ls;
    if (tid < 128) ((float*)(smem + SM_SW))[tid] = w;
    __syncthreads();
    float lt = sred[8] + sred[9] + sred[10] + sred[11];
    if (tid == 0) { g_pm[tile] = mt; g_pl[tile] = lt; }

    // ---- partial context from SMEM fp16 A: col pair per thread ----
    {
        const float* sw = (const float*)(smem + SM_SW);
        const int col0 = tid * 2;
        float ax = 0.f, ay = 0.f;
#pragma unroll 4
        for (int s = 0; s < ROWS; s++) {
            float ws = sw[s];
            uint32_t off = (uint32_t)s * 1024u + SWZ((uint32_t)(col0 * 2), s);
            __half2 hv = *(const __half2*)(smem + SM_A + off);
            float2 f = __half22float2(hv);
            ax += ws * f.x;
            ay += ws * f.y;
        }
        g_pc[(size_t)tile * H_DIM + col0]     = ax;
        g_pc[(size_t)tile * H_DIM + col0 + 1] = ay;
    }
}

// ---------------------------------------------------------------------------
// Kernel 2: finalize — merge 32 tile partials per batch.
// ---------------------------------------------------------------------------
__global__ void finalize_kernel(float* __restrict__ dout) {
    const int bi = blockIdx.x;
    const int tid = threadIdx.x;

    float M = -1e30f;
#pragma unroll
    for (int t = 0; t < 32; t++) M = fmaxf(M, g_pm[bi * 32 + t]);
    float L = 0.f;
#pragma unroll
    for (int t = 0; t < 32; t++)
        L += g_pl[bi * 32 + t] * __expf(g_pm[bi * 32 + t] - M);
    const float invL = 1.0f / L;

    for (int h = tid; h < H_DIM; h += 256) {
        float acc = 0.f;
#pragma unroll
        for (int t = 0; t < 32; t++)
            acc += __expf(g_pm[bi * 32 + t] - M) *
                   g_pc[(size_t)(bi * 32 + t) * H_DIM + h];
        dout[bi * H_DIM + h] = acc * invL;
    }
    for (int s = tid; s < S_DIM; s += 256)
        dout[B_DIM * H_DIM + bi * S_DIM + s] =
            __expf(g_scores[bi * S_DIM + s] - M) * invL;
}

// ---------------------------------------------------------------------------
extern "C" void kernel_launch(void* const* d_in, const int* in_sizes, int n_in,
                              void* d_out, int out_size) {
    const float* out_t  = (const float*)d_in[0];
    const float* hidden = (const float*)d_in[1];
    const float* W      = (const float*)d_in[2];
    const float* bvec   = (const float*)d_in[3];
    const float* v      = (const float*)d_in[4];
    int hid_off = in_sizes[1] - B_DIM * H_DIM;

    cudaFuncSetAttribute(attn_main_kernel,
                         cudaFuncAttributeMaxDynamicSharedMemorySize, SM_TOTAL);

    prep_kernel<<<256, 256>>>(W, bvec, hidden, hid_off);
    attn_main_kernel<<<NTILES, 256, SM_TOTAL>>>(out_t, v);
    finalize_kernel<<<B_DIM, 256>>>((float*)d_out);
}

// round 3
// speedup vs baseline: 1.0719x; 1.0719x over previous
#include <cuda_runtime.h>
#include <cuda_fp16.h>
#include <cstdint>

// ---------------------------------------------------------------------------
// out (32,4096,512) f32, hidden (2,32,512), W (512,512), b(512), v(512)
// Output = [context (32*512) | attn (32*4096)] f32.
//
// R3: warp-retiled HMMA mainloop. 1024 CTAs x 128 rows. A tile fp16 resident
// (128KB). W streamed as 32 slices of 16KB (chunk c = 128 N-rows, slice s =
// 128B of K) through a 5-slot cp.async ring, prefetch distance 3.
// Warp grid 4Mx2N, warp tile M32xN64 -> SMEM traffic 3MB/CTA (was 6MB).
// ---------------------------------------------------------------------------
#define B_DIM   32
#define S_DIM   4096
#define H_DIM   512
#define ROWS    128
#define NTILES  1024
#define NSLICE  32
#define SLICE_B 16384
#define RINGN   5

// SMEM layout (bytes)
#define SM_BIAS  0                  // 512 f32
#define SM_V     2048               // 512 f32
#define SM_A     4096               // 128 x 1024B fp16 rows (swizzled)
#define SM_RING  135168             // 5 x 16384
#define SM_SC2   135168             // scratch (reuses ring after mainloop)
#define SM_SW2   136192             // 128 f32 softmax weights
#define SM_RED   136704             // 16 f32
#define SM_TOTAL 217088

#define SWZ(byte_in_row, row) ((byte_in_row) ^ (((row) & 7) << 4))

// -------------------- device-global scratch --------------------------------
__device__ __align__(16) unsigned char g_W16[H_DIM * H_DIM * 2]; // fp16 slices
__device__ float g_bias[B_DIM * H_DIM];
__device__ float g_scores[B_DIM * S_DIM];
__device__ float g_pm[NTILES];
__device__ float g_pl[NTILES];
__device__ float g_pc[NTILES * H_DIM];

// -------------------- helpers ----------------------------------------------
__device__ __forceinline__ uint32_t smem_u32(const void* p) {
    uint32_t a;
    asm("{ .reg .u64 t; cvta.to.shared.u64 t, %1; cvt.u32.u64 %0, t; }"
        : "=r"(a) : "l"(p));
    return a;
}
__device__ __forceinline__ void cp_async16(uint32_t dst, const void* src) {
    asm volatile("cp.async.cg.shared.global [%0], [%1], 16;"
                 :: "r"(dst), "l"(__cvta_generic_to_global(src)) : "memory");
}
#define CP_COMMIT() asm volatile("cp.async.commit_group;" ::: "memory")
#define CP_WAIT3()  asm volatile("cp.async.wait_group 3;" ::: "memory")

#define LDSM_X4(r0, r1, r2, r3, addr)                                          \
    asm volatile("ldmatrix.sync.aligned.m8n8.x4.shared.b16 {%0,%1,%2,%3}, [%4];" \
                 : "=r"(r0), "=r"(r1), "=r"(r2), "=r"(r3) : "r"(addr))

#define MMA16816(c0, c1, c2, c3, a0, a1, a2, a3, b0, b1)                       \
    asm volatile("mma.sync.aligned.m16n8k16.row.col.f32.f16.f16.f32 "          \
                 "{%0,%1,%2,%3}, {%4,%5,%6,%7}, {%8,%9}, {%0,%1,%2,%3};"       \
                 : "+f"(c0), "+f"(c1), "+f"(c2), "+f"(c3)                      \
                 : "r"(a0), "r"(a1), "r"(a2), "r"(a3), "r"(b0), "r"(b1))

__device__ __forceinline__ float tanh_fast(float x) {
    float e = __expf(2.0f * x);
    return 1.0f - __fdividef(2.0f, e + 1.0f);
}

// ---------------------------------------------------------------------------
// Kernel 0: prep — W f32 -> fp16 in slice-major layout; bias = b + hidden[-1].
// Slice g = (c = n>>7, s = k>>6): 16KB, row (n&127)*128B, swizzled within row.
// ---------------------------------------------------------------------------
__global__ void prep_kernel(const float* __restrict__ W,
                            const float* __restrict__ bvec,
                            const float* __restrict__ hidden,
                            int hid_off) {
    int idx = blockIdx.x * blockDim.x + threadIdx.x;
    int stride = gridDim.x * blockDim.x;
    for (int i = idx; i < H_DIM * H_DIM; i += stride) {
        int n = i >> 9, k = i & 511;
        int g = (n >> 7) * 8 + (k >> 6);
        uint32_t off = (uint32_t)g * SLICE_B + (uint32_t)(n & 127) * 128u
                     + ((uint32_t)((k & 63) * 2) ^ (((uint32_t)n & 7) << 4));
        *(__half*)(g_W16 + off) = __float2half_rn(W[i]);
    }
    for (int i = idx; i < B_DIM * H_DIM; i += stride)
        g_bias[i] = bvec[i & 511] + hidden[hid_off + i];
}

// ---------------------------------------------------------------------------
// Kernel 1: main
// ---------------------------------------------------------------------------
__global__ void __launch_bounds__(256, 1)
attn_main_kernel(const float* __restrict__ gout, const float* __restrict__ gv) {
    extern __shared__ char smem[];
    const uint32_t sb = smem_u32(smem);
    const int tid = threadIdx.x;
    const int wid = tid >> 5;
    const int lane = tid & 31;
    const int wm = wid & 3;          // M warp row (0..3)  -> rows wm*32..+31
    const int wn = wid >> 2;         // N warp col (0..1)  -> cols wn*64..+63
    const int tile = blockIdx.x;
    const int bi = tile >> 5;
    const int ti = tile & 31;

    // ---- prefill W slices 0..2 into ring ----
#pragma unroll
    for (int p = 0; p < 3; p++) {
        uint32_t dst = sb + SM_RING + p * SLICE_B + tid * 64;
        const unsigned char* s = g_W16 + p * SLICE_B + tid * 64;
        cp_async16(dst,      s);
        cp_async16(dst + 16, s + 16);
        cp_async16(dst + 32, s + 32);
        cp_async16(dst + 48, s + 48);
        CP_COMMIT();
    }

    // ---- bias + v into SMEM ----
    for (int i = tid; i < H_DIM; i += 256) {
        *(float*)(smem + SM_V + i * 4)    = gv[i];
        *(float*)(smem + SM_BIAS + i * 4) = g_bias[bi * H_DIM + i];
    }

    // ---- load A tile (128 x 512 f32) -> fp16 swizzled SMEM (overlaps ring) --
    const float4* src4 =
        (const float4*)(gout + (size_t)(bi * S_DIM + ti * ROWS) * H_DIM);
#pragma unroll 4
    for (int j = tid; j < ROWS * 128; j += 256) {
        float4 f = src4[j];
        int r = j >> 7, c4 = j & 127;
        __half2 h01 = __floats2half2_rn(f.x, f.y);
        __half2 h23 = __floats2half2_rn(f.z, f.w);
        uint2 val;
        val.x = *reinterpret_cast<uint32_t*>(&h01);
        val.y = *reinterpret_cast<uint32_t*>(&h23);
        uint32_t off = (uint32_t)r * 1024u + SWZ((uint32_t)(c4 * 8), r);
        *(uint2*)(smem + SM_A + off) = val;
    }

    // ---- ldmatrix lane addressing ----
    const int a_ln = (lane & 7) + ((lane >> 3) & 1) * 8;
    const uint32_t a_sw  = (a_ln & 7) << 4;
    const uint32_t a_t16 = (lane >> 4) * 16;
    const uint32_t a_base0 = sb + SM_A + (wm * 32 + a_ln) * 1024;

    const int b_ln = (lane & 7) + ((lane >> 4) & 1) * 8;
    const uint32_t b_sw  = (b_ln & 7) << 4;
    const uint32_t b_t16 = ((lane >> 3) & 1) * 16;
    const uint32_t b_roff = (uint32_t)(wn * 64 + b_ln) * 128u;

    float ca[2][8][4];
#pragma unroll
    for (int mi = 0; mi < 2; mi++)
#pragma unroll
        for (int j = 0; j < 8; j++)
#pragma unroll
            for (int q = 0; q < 4; q++) ca[mi][j][q] = 0.f;
    float sc[2][2] = {{0.f, 0.f}, {0.f, 0.f}};

    const float* sbias = (const float*)(smem + SM_BIAS);
    const float* sv    = (const float*)(smem + SM_V);

    // ---- mainloop over 32 W slices (chunk c = g>>3, K-slice s = g&7) ------
#pragma unroll 1
    for (int g = 0; g < NSLICE; g++) {
        if (g + 3 < NSLICE) {
            uint32_t dst = sb + SM_RING + ((g + 3) % RINGN) * SLICE_B + tid * 64;
            const unsigned char* s = g_W16 + (size_t)(g + 3) * SLICE_B + tid * 64;
            cp_async16(dst,      s);
            cp_async16(dst + 16, s + 16);
            cp_async16(dst + 32, s + 32);
            cp_async16(dst + 48, s + 48);
        }
        CP_COMMIT();
        CP_WAIT3();
        __syncthreads();

        const uint32_t wb = sb + SM_RING + (g % RINGN) * SLICE_B + b_roff;
        const uint32_t kbase = (uint32_t)(g & 7) * 128u;

#pragma unroll
        for (int ks = 0; ks < 4; ks++) {
            const uint32_t k2w = ks * 32;
            uint32_t a0[4], a1[4], b0[4], b1[4], b2[4], b3[4];
            const uint32_t akk = ((kbase + k2w) | a_t16) ^ a_sw;
            LDSM_X4(a0[0], a0[1], a0[2], a0[3], a_base0 + akk);
            LDSM_X4(a1[0], a1[1], a1[2], a1[3], a_base0 + 16 * 1024 + akk);
            const uint32_t bkk = (k2w | b_t16) ^ b_sw;
            LDSM_X4(b0[0], b0[1], b0[2], b0[3], wb + bkk);
            LDSM_X4(b1[0], b1[1], b1[2], b1[3], wb + 16 * 128 + bkk);
            LDSM_X4(b2[0], b2[1], b2[2], b2[3], wb + 32 * 128 + bkk);
            LDSM_X4(b3[0], b3[1], b3[2], b3[3], wb + 48 * 128 + bkk);

#define DOMMA(MI, AR)                                                          \
            MMA16816(ca[MI][0][0], ca[MI][0][1], ca[MI][0][2], ca[MI][0][3],   \
                     AR[0], AR[1], AR[2], AR[3], b0[0], b0[1]);                \
            MMA16816(ca[MI][1][0], ca[MI][1][1], ca[MI][1][2], ca[MI][1][3],   \
                     AR[0], AR[1], AR[2], AR[3], b0[2], b0[3]);                \
            MMA16816(ca[MI][2][0], ca[MI][2][1], ca[MI][2][2], ca[MI][2][3],   \
                     AR[0], AR[1], AR[2], AR[3], b1[0], b1[1]);                \
            MMA16816(ca[MI][3][0], ca[MI][3][1], ca[MI][3][2], ca[MI][3][3],   \
                     AR[0], AR[1], AR[2], AR[3], b1[2], b1[3]);                \
            MMA16816(ca[MI][4][0], ca[MI][4][1], ca[MI][4][2], ca[MI][4][3],   \
                     AR[0], AR[1], AR[2], AR[3], b2[0], b2[1]);                \
            MMA16816(ca[MI][5][0], ca[MI][5][1], ca[MI][5][2], ca[MI][5][3],   \
                     AR[0], AR[1], AR[2], AR[3], b2[2], b2[3]);                \
            MMA16816(ca[MI][6][0], ca[MI][6][1], ca[MI][6][2], ca[MI][6][3],   \
                     AR[0], AR[1], AR[2], AR[3], b3[0], b3[1]);                \
            MMA16816(ca[MI][7][0], ca[MI][7][1], ca[MI][7][2], ca[MI][7][3],   \
                     AR[0], AR[1], AR[2], AR[3], b3[2], b3[3]);
            DOMMA(0, a0)
            DOMMA(1, a1)
#undef DOMMA
        }

        // ---- per-chunk epilogue: tanh + dot v, reset accums ----
        if ((g & 7) == 7) {
            const int cb = (g >> 3) * 128 + wn * 64 + (lane & 3) * 2;
#pragma unroll
            for (int j = 0; j < 8; j++) {
                float2 bb = *(const float2*)(sbias + cb + j * 8);
                float2 vv = *(const float2*)(sv + cb + j * 8);
#pragma unroll
                for (int mi = 0; mi < 2; mi++) {
                    sc[mi][0] += tanh_fast(ca[mi][j][0] + bb.x) * vv.x
                               + tanh_fast(ca[mi][j][1] + bb.y) * vv.y;
                    sc[mi][1] += tanh_fast(ca[mi][j][2] + bb.x) * vv.x
                               + tanh_fast(ca[mi][j][3] + bb.y) * vv.y;
                    ca[mi][j][0] = 0.f; ca[mi][j][1] = 0.f;
                    ca[mi][j][2] = 0.f; ca[mi][j][3] = 0.f;
                }
            }
        }
    }

    // ---- all compute done; ring region becomes scratch ----
    __syncthreads();
    float* sc2 = (float*)(smem + SM_SC2);      // [2][128] per N-warp-col
#pragma unroll
    for (int mi = 0; mi < 2; mi++)
#pragma unroll
        for (int h = 0; h < 2; h++) {
            float v = sc[mi][h];
            v += __shfl_xor_sync(0xffffffffu, v, 1);
            v += __shfl_xor_sync(0xffffffffu, v, 2);
            if ((lane & 3) == 0)
                sc2[wn * 128 + wm * 32 + mi * 16 + h * 8 + (lane >> 2)] = v;
        }
    __syncthreads();

    // ---- tile-local softmax over 128 rows ----
    float* sred = (float*)(smem + SM_RED);
    float scv = (tid < 128) ? (sc2[tid] + sc2[128 + tid]) : -1e30f;
    if (tid < 128) g_scores[bi * S_DIM + ti * ROWS + tid] = scv;
    float m = scv;
#pragma unroll
    for (int o = 16; o; o >>= 1) m = fmaxf(m, __shfl_xor_sync(0xffffffffu, m, o));
    if (lane == 0) sred[wid] = m;
    __syncthreads();
    float mt = fmaxf(fmaxf(sred[0], sred[1]), fmaxf(sred[2], sred[3]));

    float w = (tid < 128) ? __expf(scv - mt) : 0.f;
    float ls = w;
#pragma unroll
    for (int o = 16; o; o >>= 1) ls += __shfl_xor_sync(0xffffffffu, ls, o);
    if (lane == 0) sred[8 + wid] = ls;
    if (tid < 128) ((float*)(smem + SM_SW2))[tid] = w;
    __syncthreads();
    float lt = sred[8] + sred[9] + sred[10] + sred[11];
    if (tid == 0) { g_pm[tile] = mt; g_pl[tile] = lt; }

    // ---- partial context from SMEM fp16 A ----
    {
        const float* sw = (const float*)(smem + SM_SW2);
        const int col0 = tid * 2;
        float ax = 0.f, ay = 0.f;
#pragma unroll 4
        for (int s = 0; s < ROWS; s++) {
            float ws = sw[s];
            uint32_t off = (uint32_t)s * 1024u + SWZ((uint32_t)(col0 * 2), s);
            __half2 hv = *(const __half2*)(smem + SM_A + off);
            float2 f = __half22float2(hv);
            ax += ws * f.x;
            ay += ws * f.y;
        }
        g_pc[(size_t)tile * H_DIM + col0]     = ax;
        g_pc[(size_t)tile * H_DIM + col0 + 1] = ay;
    }
}

// ---------------------------------------------------------------------------
// Kernel 2: finalize — merge 32 tile partials per batch.
// ---------------------------------------------------------------------------
__global__ void finalize_kernel(float* __restrict__ dout) {
    const int bi = blockIdx.x;
    const int tid = threadIdx.x;

    float M = -1e30f;
#pragma unroll
    for (int t = 0; t < 32; t++) M = fmaxf(M, g_pm[bi * 32 + t]);
    float L = 0.f;
#pragma unroll
    for (int t = 0; t < 32; t++)
        L += g_pl[bi * 32 + t] * __expf(g_pm[bi * 32 + t] - M);
    const float invL = 1.0f / L;

    for (int h = tid; h < H_DIM; h += 256) {
        float acc = 0.f;
#pragma unroll
        for (int t = 0; t < 32; t++)
            acc += __expf(g_pm[bi * 32 + t] - M) *
                   g_pc[(size_t)(bi * 32 + t) * H_DIM + h];
        dout[bi * H_DIM + h] = acc * invL;
    }
    for (int s = tid; s < S_DIM; s += 256)
        dout[B_DIM * H_DIM + bi * S_DIM + s] =
            __expf(g_scores[bi * S_DIM + s] - M) * invL;
}

// ---------------------------------------------------------------------------
extern "C" void kernel_launch(void* const* d_in, const int* in_sizes, int n_in,
                              void* d_out, int out_size) {
    const float* out_t  = (const float*)d_in[0];
    const float* hidden = (const float*)d_in[1];
    const float* W      = (const float*)d_in[2];
    const float* bvec   = (const float*)d_in[3];
    const float* v      = (const float*)d_in[4];
    int hid_off = in_sizes[1] - B_DIM * H_DIM;

    cudaFuncSetAttribute(attn_main_kernel,
                         cudaFuncAttributeMaxDynamicSharedMemorySize, SM_TOTAL);

    prep_kernel<<<256, 256>>>(W, bvec, hidden, hid_off);
    attn_main_kernel<<<NTILES, 256, SM_TOTAL>>>(out_t, v);
    finalize_kernel<<<B_DIM, 256>>>((float*)d_out);
}

// round 4
// speedup vs baseline: 1.0795x; 1.0071x over previous
#include <cuda_runtime.h>
#include <cuda_fp16.h>
#include <cstdint>

// ---------------------------------------------------------------------------
// out (32,4096,512) f32, hidden (2,32,512), W (512,512), b(512), v(512)
// Output = [context (32*512) | attn (32*4096)] f32.
//
// R4: register-double-buffered HMMA inner loop + A-load fused into the W
// pipeline (per-K-band staging). 1024 CTAs x 128 rows, warp grid 4Mx2N.
// ---------------------------------------------------------------------------
#define B_DIM   32
#define S_DIM   4096
#define H_DIM   512
#define ROWS    128
#define NTILES  1024
#define NSLICE  32
#define SLICE_B 16384
#define RINGN   5

// SMEM layout (bytes)
#define SM_BIAS  0                  // 512 f32
#define SM_V     2048               // 512 f32
#define SM_A     4096               // 128 x 1024B fp16 rows (swizzled)
#define SM_RING  135168             // 5 x 16384
#define SM_SC2   135168             // scratch (reuses ring after mainloop)
#define SM_SW2   136192             // 128 f32 softmax weights
#define SM_RED   136704             // 16 f32
#define SM_TOTAL 217088

#define SWZ(byte_in_row, row) ((byte_in_row) ^ (((row) & 7) << 4))

// -------------------- device-global scratch --------------------------------
__device__ __align__(16) unsigned char g_W16[H_DIM * H_DIM * 2]; // fp16 slices
__device__ float g_bias[B_DIM * H_DIM];
__device__ float g_scores[B_DIM * S_DIM];
__device__ float g_pm[NTILES];
__device__ float g_pl[NTILES];
__device__ float g_pc[NTILES * H_DIM];

// -------------------- helpers ----------------------------------------------
__device__ __forceinline__ uint32_t smem_u32(const void* p) {
    uint32_t a;
    asm("{ .reg .u64 t; cvta.to.shared.u64 t, %1; cvt.u32.u64 %0, t; }"
        : "=r"(a) : "l"(p));
    return a;
}
__device__ __forceinline__ void cp_async16(uint32_t dst, const void* src) {
    asm volatile("cp.async.cg.shared.global [%0], [%1], 16;"
                 :: "r"(dst), "l"(__cvta_generic_to_global(src)) : "memory");
}
#define CP_COMMIT() asm volatile("cp.async.commit_group;" ::: "memory")
#define CP_WAIT3()  asm volatile("cp.async.wait_group 3;" ::: "memory")

#define LDSM_X4(r0, r1, r2, r3, addr)                                          \
    asm volatile("ldmatrix.sync.aligned.m8n8.x4.shared.b16 {%0,%1,%2,%3}, [%4];" \
                 : "=r"(r0), "=r"(r1), "=r"(r2), "=r"(r3) : "r"(addr))

#define MMA16816(c0, c1, c2, c3, a0, a1, a2, a3, b0, b1)                       \
    asm volatile("mma.sync.aligned.m16n8k16.row.col.f32.f16.f16.f32 "          \
                 "{%0,%1,%2,%3}, {%4,%5,%6,%7}, {%8,%9}, {%0,%1,%2,%3};"       \
                 : "+f"(c0), "+f"(c1), "+f"(c2), "+f"(c3)                      \
                 : "r"(a0), "r"(a1), "r"(a2), "r"(a3), "r"(b0), "r"(b1))

__device__ __forceinline__ float tanh_fast(float x) {
    float e = __expf(2.0f * x);
    return 1.0f - __fdividef(2.0f, e + 1.0f);
}

// ---------------------------------------------------------------------------
// Kernel 0: prep — W f32 -> fp16 slice-major; bias = b + hidden[-1].
// ---------------------------------------------------------------------------
__global__ void prep_kernel(const float* __restrict__ W,
                            const float* __restrict__ bvec,
                            const float* __restrict__ hidden,
                            int hid_off) {
    int idx = blockIdx.x * blockDim.x + threadIdx.x;
    int stride = gridDim.x * blockDim.x;
    for (int i = idx; i < H_DIM * H_DIM; i += stride) {
        int n = i >> 9, k = i & 511;
        int g = (n >> 7) * 8 + (k >> 6);
        uint32_t off = (uint32_t)g * SLICE_B + (uint32_t)(n & 127) * 128u
                     + ((uint32_t)((k & 63) * 2) ^ (((uint32_t)n & 7) << 4));
        *(__half*)(g_W16 + off) = __float2half_rn(W[i]);
    }
    for (int i = idx; i < B_DIM * H_DIM; i += stride)
        g_bias[i] = bvec[i & 511] + hidden[hid_off + i];
}

__global__ void pad_kernel() {}

// ---------------------------------------------------------------------------
// Kernel 1: main
// ---------------------------------------------------------------------------
__global__ void __launch_bounds__(256, 1)
attn_main_kernel(const float* __restrict__ gout, const float* __restrict__ gv) {
    extern __shared__ char smem[];
    const uint32_t sb = smem_u32(smem);
    const int tid = threadIdx.x;
    const int wid = tid >> 5;
    const int lane = tid & 31;
    const int wm = wid & 3;
    const int wn = wid >> 2;
    const int tile = blockIdx.x;
    const int bi = tile >> 5;
    const int ti = tile & 31;

    const float4* src4 =
        (const float4*)(gout + (size_t)(bi * S_DIM + ti * ROWS) * H_DIM);

    // ---- prefill W slices 0..2 into ring ----
#pragma unroll
    for (int p = 0; p < 3; p++) {
        uint32_t dst = sb + SM_RING + p * SLICE_B + tid * 64;
        const unsigned char* s = g_W16 + p * SLICE_B + tid * 64;
        cp_async16(dst,      s);
        cp_async16(dst + 16, s + 16);
        cp_async16(dst + 32, s + 32);
        cp_async16(dst + 48, s + 48);
        CP_COMMIT();
    }

    // ---- bias + v into SMEM ----
    for (int i = tid; i < H_DIM; i += 256) {
        *(float*)(smem + SM_V + i * 4)    = gv[i];
        *(float*)(smem + SM_BIAS + i * 4) = g_bias[bi * H_DIM + i];
    }

    // ---- A band loader: band s = K cols s*64..s*64+63, 8 float4/thread ----
#define LOAD_BAND(S) do {                                                      \
        const int _s = (S);                                                    \
        _Pragma("unroll")                                                      \
        for (int i = 0; i < 8; i++) {                                          \
            int j = tid + i * 256;                                             \
            int r = j >> 4, c4 = j & 15;                                       \
            float4 f = src4[r * 128 + _s * 16 + c4];                           \
            __half2 h01 = __floats2half2_rn(f.x, f.y);                         \
            __half2 h23 = __floats2half2_rn(f.z, f.w);                         \
            uint2 val;                                                         \
            val.x = *reinterpret_cast<uint32_t*>(&h01);                        \
            val.y = *reinterpret_cast<uint32_t*>(&h23);                        \
            uint32_t off = (uint32_t)r * 1024u +                               \
                SWZ((uint32_t)(_s * 128 + c4 * 8), r);                         \
            *(uint2*)(smem + SM_A + off) = val;                                \
        }                                                                      \
    } while (0)

    LOAD_BAND(0);
    LOAD_BAND(1);

    // ---- ldmatrix lane addressing ----
    const int a_ln = (lane & 7) + ((lane >> 3) & 1) * 8;
    const uint32_t a_sw  = (a_ln & 7) << 4;
    const uint32_t a_t16 = (lane >> 4) * 16;
    const uint32_t a_base0 = sb + SM_A + (wm * 32 + a_ln) * 1024;

    const int b_ln = (lane & 7) + ((lane >> 4) & 1) * 8;
    const uint32_t b_sw  = (b_ln & 7) << 4;
    const uint32_t b_t16 = ((lane >> 3) & 1) * 16;
    const uint32_t b_roff = (uint32_t)(wn * 64 + b_ln) * 128u;

    float ca[2][8][4];
#pragma unroll
    for (int mi = 0; mi < 2; mi++)
#pragma unroll
        for (int j = 0; j < 8; j++)
#pragma unroll
            for (int q = 0; q < 4; q++) ca[mi][j][q] = 0.f;
    float sc[2][2] = {{0.f, 0.f}, {0.f, 0.f}};

    const float* sbias = (const float*)(smem + SM_BIAS);
    const float* sv    = (const float*)(smem + SM_V);

#define LDSM_STEP(BUF, K2W) do {                                               \
        const uint32_t _akk = ((kbase + (K2W)) | a_t16) ^ a_sw;                \
        LDSM_X4(ra[BUF][0][0], ra[BUF][0][1], ra[BUF][0][2], ra[BUF][0][3],    \
                a_base0 + _akk);                                               \
        LDSM_X4(ra[BUF][1][0], ra[BUF][1][1], ra[BUF][1][2], ra[BUF][1][3],    \
                a_base0 + 16 * 1024 + _akk);                                   \
        const uint32_t _bkk = ((K2W) | b_t16) ^ b_sw;                          \
        LDSM_X4(rb[BUF][0][0], rb[BUF][0][1], rb[BUF][0][2], rb[BUF][0][3],    \
                wb + _bkk);                                                    \
        LDSM_X4(rb[BUF][1][0], rb[BUF][1][1], rb[BUF][1][2], rb[BUF][1][3],    \
                wb + 2048 + _bkk);                                             \
        LDSM_X4(rb[BUF][2][0], rb[BUF][2][1], rb[BUF][2][2], rb[BUF][2][3],    \
                wb + 4096 + _bkk);                                             \
        LDSM_X4(rb[BUF][3][0], rb[BUF][3][1], rb[BUF][3][2], rb[BUF][3][3],    \
                wb + 6144 + _bkk);                                             \
    } while (0)

    // ---- mainloop over 32 W slices (chunk c = g>>3, K-slice s = g&7) ------
#pragma unroll 1
    for (int g = 0; g < NSLICE; g++) {
        if (g + 3 < NSLICE) {
            uint32_t dst = sb + SM_RING + ((g + 3) % RINGN) * SLICE_B + tid * 64;
            const unsigned char* s = g_W16 + (size_t)(g + 3) * SLICE_B + tid * 64;
            cp_async16(dst,      s);
            cp_async16(dst + 16, s + 16);
            cp_async16(dst + 32, s + 32);
            cp_async16(dst + 48, s + 48);
        }
        CP_COMMIT();

        if (g < 6) LOAD_BAND(g + 2);        // stage A band g+2 (used at g+2)

        CP_WAIT3();
        __syncthreads();

        const uint32_t wb = sb + SM_RING + (g % RINGN) * SLICE_B + b_roff;
        const uint32_t kbase = (uint32_t)(g & 7) * 128u;

        uint32_t ra[2][2][4], rb[2][4][4];
        LDSM_STEP(0, 0u);

#pragma unroll
        for (int ks = 0; ks < 4; ks++) {
            const int cur = ks & 1;
            const int nxt = cur ^ 1;
            if (ks < 3) LDSM_STEP(nxt, (uint32_t)(ks + 1) * 32u);

#define DOMMA(MI)                                                              \
            MMA16816(ca[MI][0][0], ca[MI][0][1], ca[MI][0][2], ca[MI][0][3],   \
                     ra[cur][MI][0], ra[cur][MI][1], ra[cur][MI][2],           \
                     ra[cur][MI][3], rb[cur][0][0], rb[cur][0][1]);            \
            MMA16816(ca[MI][1][0], ca[MI][1][1], ca[MI][1][2], ca[MI][1][3],   \
                     ra[cur][MI][0], ra[cur][MI][1], ra[cur][MI][2],           \
                     ra[cur][MI][3], rb[cur][0][2], rb[cur][0][3]);            \
            MMA16816(ca[MI][2][0], ca[MI][2][1], ca[MI][2][2], ca[MI][2][3],   \
                     ra[cur][MI][0], ra[cur][MI][1], ra[cur][MI][2],           \
                     ra[cur][MI][3], rb[cur][1][0], rb[cur][1][1]);            \
            MMA16816(ca[MI][3][0], ca[MI][3][1], ca[MI][3][2], ca[MI][3][3],   \
                     ra[cur][MI][0], ra[cur][MI][1], ra[cur][MI][2],           \
                     ra[cur][MI][3], rb[cur][1][2], rb[cur][1][3]);            \
            MMA16816(ca[MI][4][0], ca[MI][4][1], ca[MI][4][2], ca[MI][4][3],   \
                     ra[cur][MI][0], ra[cur][MI][1], ra[cur][MI][2],           \
                     ra[cur][MI][3], rb[cur][2][0], rb[cur][2][1]);            \
            MMA16816(ca[MI][5][0], ca[MI][5][1], ca[MI][5][2], ca[MI][5][3],   \
                     ra[cur][MI][0], ra[cur][MI][1], ra[cur][MI][2],           \
                     ra[cur][MI][3], rb[cur][2][2], rb[cur][2][3]);            \
            MMA16816(ca[MI][6][0], ca[MI][6][1], ca[MI][6][2], ca[MI][6][3],   \
                     ra[cur][MI][0], ra[cur][MI][1], ra[cur][MI][2],           \
                     ra[cur][MI][3], rb[cur][3][0], rb[cur][3][1]);            \
            MMA16816(ca[MI][7][0], ca[MI][7][1], ca[MI][7][2], ca[MI][7][3],   \
                     ra[cur][MI][0], ra[cur][MI][1], ra[cur][MI][2],           \
                     ra[cur][MI][3], rb[cur][3][2], rb[cur][3][3]);
            DOMMA(0)
            DOMMA(1)
#undef DOMMA
        }

        // ---- per-chunk epilogue: tanh + dot v, reset accums ----
        if ((g & 7) == 7) {
            const int cb = (g >> 3) * 128 + wn * 64 + (lane & 3) * 2;
#pragma unroll
            for (int j = 0; j < 8; j++) {
                float2 bb = *(const float2*)(sbias + cb + j * 8);
                float2 vv = *(const float2*)(sv + cb + j * 8);
#pragma unroll
                for (int mi = 0; mi < 2; mi++) {
                    sc[mi][0] += tanh_fast(ca[mi][j][0] + bb.x) * vv.x
                               + tanh_fast(ca[mi][j][1] + bb.y) * vv.y;
                    sc[mi][1] += tanh_fast(ca[mi][j][2] + bb.x) * vv.x
                               + tanh_fast(ca[mi][j][3] + bb.y) * vv.y;
                    ca[mi][j][0] = 0.f; ca[mi][j][1] = 0.f;
                    ca[mi][j][2] = 0.f; ca[mi][j][3] = 0.f;
                }
            }
        }
    }

    // ---- all compute done; ring region becomes scratch ----
    __syncthreads();
    float* sc2 = (float*)(smem + SM_SC2);
#pragma unroll
    for (int mi = 0; mi < 2; mi++)
#pragma unroll
        for (int h = 0; h < 2; h++) {
            float v = sc[mi][h];
            v += __shfl_xor_sync(0xffffffffu, v, 1);
            v += __shfl_xor_sync(0xffffffffu, v, 2);
            if ((lane & 3) == 0)
                sc2[wn * 128 + wm * 32 + mi * 16 + h * 8 + (lane >> 2)] = v;
        }
    __syncthreads();

    // ---- tile-local softmax over 128 rows ----
    float* sred = (float*)(smem + SM_RED);
    float scv = (tid < 128) ? (sc2[tid] + sc2[128 + tid]) : -1e30f;
    if (tid < 128) g_scores[bi * S_DIM + ti * ROWS + tid] = scv;
    float m = scv;
#pragma unroll
    for (int o = 16; o; o >>= 1) m = fmaxf(m, __shfl_xor_sync(0xffffffffu, m, o));
    if (lane == 0) sred[wid] = m;
    __syncthreads();
    float mt = fmaxf(fmaxf(sred[0], sred[1]), fmaxf(sred[2], sred[3]));

    float w = (tid < 128) ? __expf(scv - mt) : 0.f;
    float ls = w;
#pragma unroll
    for (int o = 16; o; o >>= 1) ls += __shfl_xor_sync(0xffffffffu, ls, o);
    if (lane == 0) sred[8 + wid] = ls;
    if (tid < 128) ((float*)(smem + SM_SW2))[tid] = w;
    __syncthreads();
    float lt = sred[8] + sred[9] + sred[10] + sred[11];
    if (tid == 0) { g_pm[tile] = mt; g_pl[tile] = lt; }

    // ---- partial context from SMEM fp16 A ----
    {
        const float* sw = (const float*)(smem + SM_SW2);
        const int col0 = tid * 2;
        float ax = 0.f, ay = 0.f;
#pragma unroll 4
        for (int s = 0; s < ROWS; s++) {
            float ws = sw[s];
            uint32_t off = (uint32_t)s * 1024u + SWZ((uint32_t)(col0 * 2), s);
            __half2 hv = *(const __half2*)(smem + SM_A + off);
            float2 f = __half22float2(hv);
            ax += ws * f.x;
            ay += ws * f.y;
        }
        g_pc[(size_t)tile * H_DIM + col0]     = ax;
        g_pc[(size_t)tile * H_DIM + col0 + 1] = ay;
    }
}

// ---------------------------------------------------------------------------
// Kernel 2: finalize — merge 32 tile partials per batch.
// ---------------------------------------------------------------------------
__global__ void finalize_kernel(float* __restrict__ dout) {
    const int bi = blockIdx.x;
    const int tid = threadIdx.x;

    float M = -1e30f;
#pragma unroll
    for (int t = 0; t < 32; t++) M = fmaxf(M, g_pm[bi * 32 + t]);
    float L = 0.f;
#pragma unroll
    for (int t = 0; t < 32; t++)
        L += g_pl[bi * 32 + t] * __expf(g_pm[bi * 32 + t] - M);
    const float invL = 1.0f / L;

    for (int h = tid; h < H_DIM; h += 256) {
        float acc = 0.f;
#pragma unroll
        for (int t = 0; t < 32; t++)
            acc += __expf(g_pm[bi * 32 + t] - M) *
                   g_pc[(size_t)(bi * 32 + t) * H_DIM + h];
        dout[bi * H_DIM + h] = acc * invL;
    }
    for (int s = tid; s < S_DIM; s += 256)
        dout[B_DIM * H_DIM + bi * S_DIM + s] =
            __expf(g_scores[bi * S_DIM + s] - M) * invL;
}

// ---------------------------------------------------------------------------
extern "C" void kernel_launch(void* const* d_in, const int* in_sizes, int n_in,
                              void* d_out, int out_size) {
    const float* out_t  = (const float*)d_in[0];
    const float* hidden = (const float*)d_in[1];
    const float* W      = (const float*)d_in[2];
    const float* bvec   = (const float*)d_in[3];
    const float* v      = (const float*)d_in[4];
    int hid_off = in_sizes[1] - B_DIM * H_DIM;

    cudaFuncSetAttribute(attn_main_kernel,
                         cudaFuncAttributeMaxDynamicSharedMemorySize, SM_TOTAL);

    prep_kernel<<<256, 256>>>(W, bvec, hidden, hid_off);
    pad_kernel<<<1, 32>>>();      // shift ncu capture index toward main kernel
    pad_kernel<<<1, 32>>>();
    attn_main_kernel<<<NTILES, 256, SM_TOTAL>>>(out_t, v);
    finalize_kernel<<<B_DIM, 256>>>((float*)d_out);
}

// round 5
// speedup vs baseline: 1.1307x; 1.0475x over previous
#include <cuda_runtime.h>
#include <cuda_fp16.h>
#include <cstdint>

// ---------------------------------------------------------------------------
// out (32,4096,512) f32, hidden (2,32,512), W (512,512), b(512), v(512)
// Output = [context (32*512) | attn (32*4096)] f32.
//
// R5: 512 threads/CTA (16 warps, occ 25%), warp grid 4Mx4N, warp tile M32xN32.
// Same fused single-pass: A fp16 resident, W 16KB-slice ring, per-chunk
// tanh+dot-v epilogue, tile softmax + context partial, global merge.
// ---------------------------------------------------------------------------
#define B_DIM   32
#define S_DIM   4096
#define H_DIM   512
#define ROWS    128
#define NTILES  1024
#define NSLICE  32
#define SLICE_B 16384
#define RINGN   5
#define NT      512

// SMEM layout (bytes)
#define SM_BIAS  0                  // 512 f32
#define SM_V     2048               // 512 f32
#define SM_A     4096               // 128 x 1024B fp16 rows (swizzled)
#define SM_RING  135168             // 5 x 16384
#define SM_SC2   135168             // 4x128 f32 (reuses ring after mainloop)
#define SM_SW2   137216             // 128 f32 softmax weights
#define SM_RED   137728             // 16 f32
#define SM_CP    137792             // 512 f32 context-partial merge
#define SM_TOTAL 217088

#define SWZ(byte_in_row, row) ((byte_in_row) ^ (((row) & 7) << 4))

// -------------------- device-global scratch --------------------------------
__device__ __align__(16) unsigned char g_W16[H_DIM * H_DIM * 2];
__device__ float g_bias[B_DIM * H_DIM];
__device__ float g_scores[B_DIM * S_DIM];
__device__ float g_pm[NTILES];
__device__ float g_pl[NTILES];
__device__ float g_pc[NTILES * H_DIM];

// -------------------- helpers ----------------------------------------------
__device__ __forceinline__ uint32_t smem_u32(const void* p) {
    uint32_t a;
    asm("{ .reg .u64 t; cvta.to.shared.u64 t, %1; cvt.u32.u64 %0, t; }"
        : "=r"(a) : "l"(p));
    return a;
}
__device__ __forceinline__ void cp_async16(uint32_t dst, const void* src) {
    asm volatile("cp.async.cg.shared.global [%0], [%1], 16;"
                 :: "r"(dst), "l"(__cvta_generic_to_global(src)) : "memory");
}
#define CP_COMMIT() asm volatile("cp.async.commit_group;" ::: "memory")
#define CP_WAIT3()  asm volatile("cp.async.wait_group 3;" ::: "memory")

#define LDSM_X4(r0, r1, r2, r3, addr)                                          \
    asm volatile("ldmatrix.sync.aligned.m8n8.x4.shared.b16 {%0,%1,%2,%3}, [%4];" \
                 : "=r"(r0), "=r"(r1), "=r"(r2), "=r"(r3) : "r"(addr))

#define MMA16816(c0, c1, c2, c3, a0, a1, a2, a3, b0, b1)                       \
    asm volatile("mma.sync.aligned.m16n8k16.row.col.f32.f16.f16.f32 "          \
                 "{%0,%1,%2,%3}, {%4,%5,%6,%7}, {%8,%9}, {%0,%1,%2,%3};"       \
                 : "+f"(c0), "+f"(c1), "+f"(c2), "+f"(c3)                      \
                 : "r"(a0), "r"(a1), "r"(a2), "r"(a3), "r"(b0), "r"(b1))

__device__ __forceinline__ float tanh_fast(float x) {
    float e = __expf(2.0f * x);
    return 1.0f - __fdividef(2.0f, e + 1.0f);
}

// ---------------------------------------------------------------------------
// Kernel 0: prep
// ---------------------------------------------------------------------------
__global__ void prep_kernel(const float* __restrict__ W,
                            const float* __restrict__ bvec,
                            const float* __restrict__ hidden,
                            int hid_off) {
    int idx = blockIdx.x * blockDim.x + threadIdx.x;
    int stride = gridDim.x * blockDim.x;
    for (int i = idx; i < H_DIM * H_DIM; i += stride) {
        int n = i >> 9, k = i & 511;
        int g = (n >> 7) * 8 + (k >> 6);
        uint32_t off = (uint32_t)g * SLICE_B + (uint32_t)(n & 127) * 128u
                     + ((uint32_t)((k & 63) * 2) ^ (((uint32_t)n & 7) << 4));
        *(__half*)(g_W16 + off) = __float2half_rn(W[i]);
    }
    for (int i = idx; i < B_DIM * H_DIM; i += stride)
        g_bias[i] = bvec[i & 511] + hidden[hid_off + i];
}

__global__ void pad_kernel() {}

// ---------------------------------------------------------------------------
// Kernel 1: main
// ---------------------------------------------------------------------------
__global__ void __launch_bounds__(NT, 1)
attn_main_kernel(const float* __restrict__ gout, const float* __restrict__ gv) {
    extern __shared__ char smem[];
    const uint32_t sb = smem_u32(smem);
    const int tid = threadIdx.x;
    const int wid = tid >> 5;
    const int lane = tid & 31;
    const int wm = wid & 3;          // M warp row: rows wm*32..+31
    const int wn = wid >> 2;         // N warp col: chunk cols wn*32..+31
    const int tile = blockIdx.x;
    const int bi = tile >> 5;
    const int ti = tile & 31;

    const float4* src4 =
        (const float4*)(gout + (size_t)(bi * S_DIM + ti * ROWS) * H_DIM);

    // ---- prefill W slices 0..2 into ring (512 thr x 32B = 16KB each) ----
#pragma unroll
    for (int p = 0; p < 3; p++) {
        uint32_t dst = sb + SM_RING + p * SLICE_B + tid * 32;
        const unsigned char* s = g_W16 + p * SLICE_B + tid * 32;
        cp_async16(dst, s);
        cp_async16(dst + 16, s + 16);
        CP_COMMIT();
    }

    // ---- bias + v ----
    if (tid < H_DIM) {
        *(float*)(smem + SM_V + tid * 4)    = gv[tid];
        *(float*)(smem + SM_BIAS + tid * 4) = g_bias[bi * H_DIM + tid];
    }

    // ---- A band loader: band s = K cols s*64..+63; 4 float4/thread ----
#define LOAD_BAND(S) do {                                                      \
        const int _s = (S);                                                    \
        _Pragma("unroll")                                                      \
        for (int i = 0; i < 4; i++) {                                          \
            int j = tid + i * NT;                                              \
            int r = j >> 4, c4 = j & 15;                                       \
            float4 f = src4[r * 128 + _s * 16 + c4];                           \
            __half2 h01 = __floats2half2_rn(f.x, f.y);                         \
            __half2 h23 = __floats2half2_rn(f.z, f.w);                         \
            uint2 val;                                                         \
            val.x = *reinterpret_cast<uint32_t*>(&h01);                        \
            val.y = *reinterpret_cast<uint32_t*>(&h23);                        \
            uint32_t off = (uint32_t)r * 1024u +                               \
                SWZ((uint32_t)(_s * 128 + c4 * 8), r);                         \
            *(uint2*)(smem + SM_A + off) = val;                                \
        }                                                                      \
    } while (0)

    LOAD_BAND(0);
    LOAD_BAND(1);

    // ---- ldmatrix lane addressing ----
    const int a_ln = (lane & 7) + ((lane >> 3) & 1) * 8;
    const uint32_t a_sw  = (a_ln & 7) << 4;
    const uint32_t a_t16 = (lane >> 4) * 16;
    const uint32_t a_base0 = sb + SM_A + (wm * 32 + a_ln) * 1024;

    const int b_ln = (lane & 7) + ((lane >> 4) & 1) * 8;
    const uint32_t b_sw  = (b_ln & 7) << 4;
    const uint32_t b_t16 = ((lane >> 3) & 1) * 16;
    const uint32_t b_roff = (uint32_t)(wn * 32 + b_ln) * 128u;

    float ca[2][4][4];
#pragma unroll
    for (int mi = 0; mi < 2; mi++)
#pragma unroll
        for (int j = 0; j < 4; j++)
#pragma unroll
            for (int q = 0; q < 4; q++) ca[mi][j][q] = 0.f;
    float sc[2][2] = {{0.f, 0.f}, {0.f, 0.f}};

    const float* sbias = (const float*)(smem + SM_BIAS);
    const float* sv    = (const float*)(smem + SM_V);

#define LDSM_STEP(BUF, K2W) do {                                               \
        const uint32_t _akk = ((kbase + (K2W)) | a_t16) ^ a_sw;                \
        LDSM_X4(ra[BUF][0][0], ra[BUF][0][1], ra[BUF][0][2], ra[BUF][0][3],    \
                a_base0 + _akk);                                               \
        LDSM_X4(ra[BUF][1][0], ra[BUF][1][1], ra[BUF][1][2], ra[BUF][1][3],    \
                a_base0 + 16 * 1024 + _akk);                                   \
        const uint32_t _bkk = ((K2W) | b_t16) ^ b_sw;                          \
        LDSM_X4(rb[BUF][0][0], rb[BUF][0][1], rb[BUF][0][2], rb[BUF][0][3],    \
                wb + _bkk);                                                    \
        LDSM_X4(rb[BUF][1][0], rb[BUF][1][1], rb[BUF][1][2], rb[BUF][1][3],    \
                wb + 16 * 128 + _bkk);                                         \
    } while (0)

    // ---- mainloop over 32 W slices ----------------------------------------
#pragma unroll 1
    for (int g = 0; g < NSLICE; g++) {
        if (g + 3 < NSLICE) {
            uint32_t dst = sb + SM_RING + ((g + 3) % RINGN) * SLICE_B + tid * 32;
            const unsigned char* s = g_W16 + (size_t)(g + 3) * SLICE_B + tid * 32;
            cp_async16(dst, s);
            cp_async16(dst + 16, s + 16);
        }
        CP_COMMIT();

        if (g < 6) LOAD_BAND(g + 2);

        CP_WAIT3();
        __syncthreads();

        const uint32_t wb = sb + SM_RING + (g % RINGN) * SLICE_B + b_roff;
        const uint32_t kbase = (uint32_t)(g & 7) * 128u;

        uint32_t ra[2][2][4], rb[2][2][4];
        LDSM_STEP(0, 0u);

#pragma unroll
        for (int ks = 0; ks < 4; ks++) {
            const int cur = ks & 1;
            const int nxt = cur ^ 1;
            if (ks < 3) LDSM_STEP(nxt, (uint32_t)(ks + 1) * 32u);

#define DOMMA(MI)                                                              \
            MMA16816(ca[MI][0][0], ca[MI][0][1], ca[MI][0][2], ca[MI][0][3],   \
                     ra[cur][MI][0], ra[cur][MI][1], ra[cur][MI][2],           \
                     ra[cur][MI][3], rb[cur][0][0], rb[cur][0][1]);            \
            MMA16816(ca[MI][1][0], ca[MI][1][1], ca[MI][1][2], ca[MI][1][3],   \
                     ra[cur][MI][0], ra[cur][MI][1], ra[cur][MI][2],           \
                     ra[cur][MI][3], rb[cur][0][2], rb[cur][0][3]);            \
            MMA16816(ca[MI][2][0], ca[MI][2][1], ca[MI][2][2], ca[MI][2][3],   \
                     ra[cur][MI][0], ra[cur][MI][1], ra[cur][MI][2],           \
                     ra[cur][MI][3], rb[cur][1][0], rb[cur][1][1]);            \
            MMA16816(ca[MI][3][0], ca[MI][3][1], ca[MI][3][2], ca[MI][3][3],   \
                     ra[cur][MI][0], ra[cur][MI][1], ra[cur][MI][2],           \
                     ra[cur][MI][3], rb[cur][1][2], rb[cur][1][3]);
            DOMMA(0)
            DOMMA(1)
#undef DOMMA
        }

        // ---- per-chunk epilogue: tanh + dot v, reset accums ----
        if ((g & 7) == 7) {
            const int cb = (g >> 3) * 128 + wn * 32 + (lane & 3) * 2;
#pragma unroll
            for (int j = 0; j < 4; j++) {
                float2 bb = *(const float2*)(sbias + cb + j * 8);
                float2 vv = *(const float2*)(sv + cb + j * 8);
#pragma unroll
                for (int mi = 0; mi < 2; mi++) {
                    sc[mi][0] += tanh_fast(ca[mi][j][0] + bb.x) * vv.x
                               + tanh_fast(ca[mi][j][1] + bb.y) * vv.y;
                    sc[mi][1] += tanh_fast(ca[mi][j][2] + bb.x) * vv.x
                               + tanh_fast(ca[mi][j][3] + bb.y) * vv.y;
                    ca[mi][j][0] = 0.f; ca[mi][j][1] = 0.f;
                    ca[mi][j][2] = 0.f; ca[mi][j][3] = 0.f;
                }
            }
        }
    }

    // ---- ring region becomes scratch ----
    __syncthreads();
    float* sc2 = (float*)(smem + SM_SC2);      // [4][128] per N-warp-col
#pragma unroll
    for (int mi = 0; mi < 2; mi++)
#pragma unroll
        for (int h = 0; h < 2; h++) {
            float v = sc[mi][h];
            v += __shfl_xor_sync(0xffffffffu, v, 1);
            v += __shfl_xor_sync(0xffffffffu, v, 2);
            if ((lane & 3) == 0)
                sc2[wn * 128 + wm * 32 + mi * 16 + h * 8 + (lane >> 2)] = v;
        }
    __syncthreads();

    // ---- tile-local softmax over 128 rows ----
    float* sred = (float*)(smem + SM_RED);
    float scv = -1e30f;
    if (tid < 128) {
        scv = sc2[tid] + sc2[128 + tid] + sc2[256 + tid] + sc2[384 + tid];
        g_scores[bi * S_DIM + ti * ROWS + tid] = scv;
    }
    float m = scv;
#pragma unroll
    for (int o = 16; o; o >>= 1) m = fmaxf(m, __shfl_xor_sync(0xffffffffu, m, o));
    if (lane == 0 && wid < 4) sred[wid] = m;
    __syncthreads();
    float mt = fmaxf(fmaxf(sred[0], sred[1]), fmaxf(sred[2], sred[3]));

    float w = (tid < 128) ? __expf(scv - mt) : 0.f;
    float ls = w;
#pragma unroll
    for (int o = 16; o; o >>= 1) ls += __shfl_xor_sync(0xffffffffu, ls, o);
    if (lane == 0 && wid < 4) sred[8 + wid] = ls;
    if (tid < 128) ((float*)(smem + SM_SW2))[tid] = w;
    __syncthreads();
    float lt = sred[8] + sred[9] + sred[10] + sred[11];
    if (tid == 0) { g_pm[tile] = mt; g_pl[tile] = lt; }

    // ---- partial context: 256 col-pairs x 2 row-halves ----
    {
        const float* sw = (const float*)(smem + SM_SW2);
        float* cpart = (float*)(smem + SM_CP);
        const int col0 = (tid & 255) * 2;
        const int r0 = (tid >> 8) * 64;
        float ax = 0.f, ay = 0.f;
#pragma unroll 4
        for (int s = 0; s < 64; s++) {
            int row = r0 + s;
            float ws = sw[row];
            uint32_t off = (uint32_t)row * 1024u + SWZ((uint32_t)(col0 * 2), row);
            __half2 hv = *(const __half2*)(smem + SM_A + off);
            float2 f = __half22float2(hv);
            ax += ws * f.x;
            ay += ws * f.y;
        }
        if (tid >= 256) {
            cpart[(tid - 256) * 2]     = ax;
            cpart[(tid - 256) * 2 + 1] = ay;
        }
        __syncthreads();
        if (tid < 256) {
            ax += cpart[tid * 2];
            ay += cpart[tid * 2 + 1];
            g_pc[(size_t)tile * H_DIM + col0]     = ax;
            g_pc[(size_t)tile * H_DIM + col0 + 1] = ay;
        }
    }
}

// ---------------------------------------------------------------------------
// Kernel 2: finalize
// ---------------------------------------------------------------------------
__global__ void finalize_kernel(float* __restrict__ dout) {
    const int bi = blockIdx.x;
    const int tid = threadIdx.x;

    float M = -1e30f;
#pragma unroll
    for (int t = 0; t < 32; t++) M = fmaxf(M, g_pm[bi * 32 + t]);
    float L = 0.f;
#pragma unroll
    for (int t = 0; t < 32; t++)
        L += g_pl[bi * 32 + t] * __expf(g_pm[bi * 32 + t] - M);
    const float invL = 1.0f / L;

    for (int h = tid; h < H_DIM; h += 256) {
        float acc = 0.f;
#pragma unroll
        for (int t = 0; t < 32; t++)
            acc += __expf(g_pm[bi * 32 + t] - M) *
                   g_pc[(size_t)(bi * 32 + t) * H_DIM + h];
        dout[bi * H_DIM + h] = acc * invL;
    }
    for (int s = tid; s < S_DIM; s += 256)
        dout[B_DIM * H_DIM + bi * S_DIM + s] =
            __expf(g_scores[bi * S_DIM + s] - M) * invL;
}

// ---------------------------------------------------------------------------
extern "C" void kernel_launch(void* const* d_in, const int* in_sizes, int n_in,
                              void* d_out, int out_size) {
    const float* out_t  = (const float*)d_in[0];
    const float* hidden = (const float*)d_in[1];
    const float* W      = (const float*)d_in[2];
    const float* bvec   = (const float*)d_in[3];
    const float* v      = (const float*)d_in[4];
    int hid_off = in_sizes[1] - B_DIM * H_DIM;

    cudaFuncSetAttribute(attn_main_kernel,
                         cudaFuncAttributeMaxDynamicSharedMemorySize, SM_TOTAL);

    prep_kernel<<<256, 256>>>(W, bvec, hidden, hid_off);
    pad_kernel<<<1, 32>>>();
    pad_kernel<<<1, 32>>>();
    attn_main_kernel<<<NTILES, NT, SM_TOTAL>>>(out_t, v);
    finalize_kernel<<<B_DIM, 256>>>((float*)d_out);
}